// round 1
// baseline (speedup 1.0000x reference)
#include <cuda_runtime.h>

#define BT 96
#define Nn 512
#define Dd 64
#define NNb 16
#define MS 45

// ---------------- device scratch (no allocations allowed) ----------------
__device__ float g_xq[BT*Nn*Dd];   // x + positional term
__device__ float g_Q [BT*Nn*Dd];
__device__ float g_K [BT*Nn*Dd];
__device__ float g_V [BT*Nn*Dd];
__device__ float g_M [BT*Nn];
__device__ int   g_top[BT*MS];
__device__ float g_attn[BT*MS*Nn];
__device__ float g_av [BT*MS*Dd];
__device__ float g_val[BT*Nn*Dd];

// ---------------- K1: x_ = x + ev ; Q,K,V = x_ @ W + b ----------------
__global__ void k_qkv(const float* __restrict__ x, const float* __restrict__ eigvec,
                      const float* __restrict__ eigval,
                      const float* __restrict__ Wq, const float* __restrict__ bq,
                      const float* __restrict__ Wk, const float* __restrict__ bk,
                      const float* __restrict__ Wv, const float* __restrict__ bv)
{
    __shared__ __align__(16) float xs[64*64];
    __shared__ __align__(16) float ws[64*64];
    __shared__ __align__(16) float bs[64];
    int bt = blockIdx.x >> 3;
    int nb = (blockIdx.x & 7) * 64;
    int tid = threadIdx.x;

    for (int idx = tid; idx < 4096; idx += 256) {
        int r = idx >> 6, d = idx & 63;
        int n = nb + r;
        float v = x[(bt*Nn + n)*Dd + d] + eigvec[d*Nn + n] * eigval[d];
        xs[idx] = v;
        g_xq[(bt*Nn + n)*Dd + d] = v;
    }

    const float* Wm[3]  = {Wq, Wk, Wv};
    const float* bm[3]  = {bq, bk, bv};
    float*       Om[3];
    Om[0] = g_Q; Om[1] = g_K; Om[2] = g_V;

    int j4 = tid & 15;     // 4-col group
    int rg = tid >> 4;     // 16 row groups x 4 rows
    for (int m = 0; m < 3; m++) {
        __syncthreads();   // xs ready / previous compute done
        for (int idx = tid; idx < 4096; idx += 256) ws[idx] = Wm[m][idx];
        if (tid < 64) bs[tid] = bm[m][tid];
        __syncthreads();
        float4 b4 = ((const float4*)bs)[j4];
        float4 acc0 = b4, acc1 = b4, acc2 = b4, acc3 = b4;
        const float4* ws4 = (const float4*)ws;
        #pragma unroll 8
        for (int d = 0; d < 64; d++) {
            float4 w4 = ws4[d*16 + j4];
            float x0 = xs[(rg*4+0)*64 + d];
            float x1 = xs[(rg*4+1)*64 + d];
            float x2 = xs[(rg*4+2)*64 + d];
            float x3 = xs[(rg*4+3)*64 + d];
            acc0.x += x0*w4.x; acc0.y += x0*w4.y; acc0.z += x0*w4.z; acc0.w += x0*w4.w;
            acc1.x += x1*w4.x; acc1.y += x1*w4.y; acc1.z += x1*w4.z; acc1.w += x1*w4.w;
            acc2.x += x2*w4.x; acc2.y += x2*w4.y; acc2.z += x2*w4.z; acc2.w += x2*w4.w;
            acc3.x += x3*w4.x; acc3.y += x3*w4.y; acc3.z += x3*w4.z; acc3.w += x3*w4.w;
        }
        float* O = Om[m];
        int nbase = (bt*Nn + nb + rg*4)*Dd;
        ((float4*)(O + nbase + 0*Dd))[j4] = acc0;
        ((float4*)(O + nbase + 1*Dd))[j4] = acc1;
        ((float4*)(O + nbase + 2*Dd))[j4] = acc2;
        ((float4*)(O + nbase + 3*Dd))[j4] = acc3;
    }
}

// ---------------- K2: neighbor GAT -> M scores ----------------
__global__ void k_gat(const int* __restrict__ adj, const float* __restrict__ Wp,
                      const float* __restrict__ bp)
{
    int warp = threadIdx.x >> 5, lane = threadIdx.x & 31;
    int g = blockIdx.x * 8 + warp;      // g in [0, BT*Nn)
    int bt = g >> 9, n = g & 511;
    int base = bt*Nn*Dd;
    float2 q = ((const float2*)(g_Q + base + n*Dd))[lane];
    float ax = 0.f, ay = 0.f;
    #pragma unroll
    for (int k = 0; k < NNb; k++) {
        int j = adj[n*NNb + k];
        float2 kk = ((const float2*)(g_K + base + j*Dd))[lane];
        float p = q.x*kk.x + q.y*kk.y;
        #pragma unroll
        for (int o = 16; o; o >>= 1) p += __shfl_xor_sync(0xffffffffu, p, o);
        float2 vv = ((const float2*)(g_V + base + j*Dd))[lane];
        ax += p*vv.x; ay += p*vv.y;
    }
    float2 wp = ((const float2*)Wp)[lane];
    float mm = ax*wp.x + ay*wp.y;
    #pragma unroll
    for (int o = 16; o; o >>= 1) mm += __shfl_xor_sync(0xffffffffu, mm, o);
    if (lane == 0) g_M[g] = mm + bp[0];
}

// ---------------- K3: top-45 of 512 (bitonic; set-equality suffices) ----------------
__global__ void k_topk()
{
    __shared__ unsigned long long key[512];
    int bt = blockIdx.x, tid = threadIdx.x;
    float f = g_M[bt*Nn + tid];
    unsigned int u = __float_as_uint(f);
    u = (u & 0x80000000u) ? ~u : (u | 0x80000000u);   // order-preserving map
    key[tid] = ((unsigned long long)u << 32) | (unsigned)tid;
    __syncthreads();
    for (int k = 2; k <= 512; k <<= 1) {
        for (int j = k >> 1; j > 0; j >>= 1) {
            int ix = tid ^ j;
            if (ix > tid) {
                bool up = ((tid & k) == 0);
                unsigned long long a = key[tid], b = key[ix];
                if ((a > b) == up) { key[tid] = b; key[ix] = a; }
            }
            __syncthreads();
        }
    }
    if (tid < MS) g_top[bt*MS + tid] = (int)(key[511 - tid] & 0xffffffffu);
}

// ---------------- K4: scores -> softmax -> attn (stored) -> av. One CTA per (b,t) ----------------
__global__ void k_attn()
{
    extern __shared__ float sm[];
    float* sc = sm;                 // 45*512 scores/attn
    float* qs = sm + MS*Nn;         // 45*64 Q_red
    float* ts = qs + MS*Dd;         // 64*65 padded K/V tile
    int bt = blockIdx.x, tid = threadIdx.x;   // 512 threads
    int base = bt*Nn*Dd;

    for (int idx = tid; idx < MS*Dd; idx += 512) {
        int m = idx >> 6, d = idx & 63;
        qs[idx] = g_Q[base + g_top[bt*MS + m]*Dd + d];
    }
    // ---- scores ----
    const float scl = 0.125f;  // 1/sqrt(64)
    for (int t = 0; t < 8; t++) {
        __syncthreads();
        for (int idx = tid; idx < 4096; idx += 512) {
            int r = idx >> 6, d = idx & 63;
            ts[r*65 + d] = g_K[base + (t*64 + r)*Dd + d];
        }
        __syncthreads();
        for (int idx = tid; idx < MS*64; idx += 512) {
            int m = idx >> 6, r = idx & 63;
            const float* qp = qs + m*64;
            const float* kp = ts + r*65;
            float s = 0.f;
            #pragma unroll
            for (int d = 0; d < 64; d++) s += qp[d]*kp[d];
            sc[m*Nn + t*64 + r] = s * scl;
        }
    }
    __syncthreads();
    // ---- softmax per m-row, write attn to smem + global ----
    int warp = tid >> 5, lane = tid & 31;
    for (int m = warp; m < MS; m += 16) {
        float* row = sc + m*Nn;
        float mx = -1e30f;
        for (int n = lane; n < Nn; n += 32) mx = fmaxf(mx, row[n]);
        #pragma unroll
        for (int o = 16; o; o >>= 1) mx = fmaxf(mx, __shfl_xor_sync(0xffffffffu, mx, o));
        float s = 0.f;
        for (int n = lane; n < Nn; n += 32) s += __expf(row[n] - mx);
        #pragma unroll
        for (int o = 16; o; o >>= 1) s += __shfl_xor_sync(0xffffffffu, s, o);
        float rinv = 1.f / s;
        float* grow = g_attn + (bt*MS + m)*Nn;
        for (int n = lane; n < Nn; n += 32) {
            float a = __expf(row[n] - mx) * rinv;
            row[n] = a;
            grow[n] = a;
        }
    }
    // ---- av = attn @ V ----
    int d = tid & 63, mg = tid >> 6;
    float acc[6];
    #pragma unroll
    for (int i = 0; i < 6; i++) acc[i] = 0.f;
    for (int t = 0; t < 8; t++) {
        __syncthreads();
        for (int idx = tid; idx < 4096; idx += 512) {
            int r = idx >> 6, dd = idx & 63;
            ts[r*65 + dd] = g_V[base + (t*64 + r)*Dd + dd];
        }
        __syncthreads();
        int mi = 0;
        for (int m = mg; m < MS; m += 8, mi++) {
            const float* arow = sc + m*Nn + t*64;
            float a = acc[mi];
            #pragma unroll
            for (int r = 0; r < 64; r++) a += arow[r] * ts[r*65 + d];
            acc[mi] = a;
        }
    }
    int mi = 0;
    for (int m = mg; m < MS; m += 8, mi++)
        g_av[(bt*MS + m)*Dd + d] = acc[mi];
}

// ---------------- K5: cp=argmax_m attn, gather av, @Wo + residual, LN ----------------
__global__ void k_value(const float* __restrict__ Wo, const float* __restrict__ bo)
{
    __shared__ float ws[4096];
    __shared__ float bs[64];
    int tid = threadIdx.x;
    for (int idx = tid; idx < 4096; idx += 256) ws[idx] = Wo[idx];
    if (tid < 64) bs[tid] = bo[tid];
    __syncthreads();
    int warp = tid >> 5, lane = tid & 31;
    for (int it = 0; it < 4; it++) {
        int g = blockIdx.x*32 + it*8 + warp;
        int bt = g >> 9, n = g & 511;
        // argmax over 45 attention rows (tie -> lowest m)
        float bv = -1e30f; int bi = 0x7fffffff;
        for (int m = lane; m < MS; m += 32) {
            float v = g_attn[(bt*MS + m)*Nn + n];
            if (v > bv) { bv = v; bi = m; }
        }
        #pragma unroll
        for (int o = 16; o; o >>= 1) {
            float ov = __shfl_xor_sync(0xffffffffu, bv, o);
            int   oi = __shfl_xor_sync(0xffffffffu, bi, o);
            if (ov > bv || (ov == bv && oi < bi)) { bv = ov; bi = oi; }
        }
        const float* av = g_av + (bt*MS + bi)*Dd;
        float a = av[lane], b = av[lane + 32];
        float olo = bs[lane], ohi = bs[lane + 32];
        #pragma unroll
        for (int dd = 0; dd < 32; dd++) {
            float xd = __shfl_sync(0xffffffffu, a, dd);
            olo += xd * ws[dd*64 + lane];
            ohi += xd * ws[dd*64 + lane + 32];
        }
        #pragma unroll
        for (int dd = 0; dd < 32; dd++) {
            float xd = __shfl_sync(0xffffffffu, b, dd);
            olo += xd * ws[(dd+32)*64 + lane];
            ohi += xd * ws[(dd+32)*64 + lane + 32];
        }
        const float* xr = g_xq + g*Dd;
        olo += xr[lane]; ohi += xr[lane + 32];
        // LayerNorm over 64
        float s = olo + ohi;
        #pragma unroll
        for (int o = 16; o; o >>= 1) s += __shfl_xor_sync(0xffffffffu, s, o);
        float mu = s * (1.f/64.f);
        float dl = olo - mu, dh = ohi - mu;
        float v2 = dl*dl + dh*dh;
        #pragma unroll
        for (int o = 16; o; o >>= 1) v2 += __shfl_xor_sync(0xffffffffu, v2, o);
        float r = rsqrtf(v2*(1.f/64.f) + 1e-5f);
        float* vo = g_val + g*Dd;
        vo[lane] = dl*r; vo[lane + 32] = dh*r;
    }
}

// ---------------- K6: FFN (relu(v@W1+b1)@W2+b2) + residual + LN -> out ----------------
__global__ void k_ffn(const float* __restrict__ W1, const float* __restrict__ b1,
                      const float* __restrict__ W2, const float* __restrict__ b2,
                      float* __restrict__ out)
{
    __shared__ float w1s[4096], w2s[4096];
    __shared__ float b1s[64], b2s[64];
    int tid = threadIdx.x;
    for (int idx = tid; idx < 4096; idx += 256) { w1s[idx] = W1[idx]; w2s[idx] = W2[idx]; }
    if (tid < 64) { b1s[tid] = b1[tid]; b2s[tid] = b2[tid]; }
    __syncthreads();
    int warp = tid >> 5, lane = tid & 31;
    for (int it = 0; it < 4; it++) {
        int g = blockIdx.x*32 + it*8 + warp;
        const float* vr = g_val + g*Dd;
        float a = vr[lane], b = vr[lane + 32];
        float tlo = b1s[lane], thi = b1s[lane + 32];
        #pragma unroll
        for (int dd = 0; dd < 32; dd++) {
            float xd = __shfl_sync(0xffffffffu, a, dd);
            tlo += xd * w1s[dd*64 + lane];
            thi += xd * w1s[dd*64 + lane + 32];
        }
        #pragma unroll
        for (int dd = 0; dd < 32; dd++) {
            float xd = __shfl_sync(0xffffffffu, b, dd);
            tlo += xd * w1s[(dd+32)*64 + lane];
            thi += xd * w1s[(dd+32)*64 + lane + 32];
        }
        tlo = fmaxf(tlo, 0.f); thi = fmaxf(thi, 0.f);
        float hlo = b2s[lane], hhi = b2s[lane + 32];
        #pragma unroll
        for (int dd = 0; dd < 32; dd++) {
            float xd = __shfl_sync(0xffffffffu, tlo, dd);
            hlo += xd * w2s[dd*64 + lane];
            hhi += xd * w2s[dd*64 + lane + 32];
        }
        #pragma unroll
        for (int dd = 0; dd < 32; dd++) {
            float xd = __shfl_sync(0xffffffffu, thi, dd);
            hlo += xd * w2s[(dd+32)*64 + lane];
            hhi += xd * w2s[(dd+32)*64 + lane + 32];
        }
        hlo += a; hhi += b;   // residual
        float s = hlo + hhi;
        #pragma unroll
        for (int o = 16; o; o >>= 1) s += __shfl_xor_sync(0xffffffffu, s, o);
        float mu = s * (1.f/64.f);
        float dl = hlo - mu, dh = hhi - mu;
        float v2 = dl*dl + dh*dh;
        #pragma unroll
        for (int o = 16; o; o >>= 1) v2 += __shfl_xor_sync(0xffffffffu, v2, o);
        float r = rsqrtf(v2*(1.f/64.f) + 1e-5f);
        out[g*Dd + lane]      = dl*r;
        out[g*Dd + lane + 32] = dh*r;
    }
}

// ---------------- launch ----------------
extern "C" void kernel_launch(void* const* d_in, const int* in_sizes, int n_in,
                              void* d_out, int out_size)
{
    const float* x      = (const float*)d_in[0];
    const int*   adj    = (const int*)  d_in[1];
    const float* eigvec = (const float*)d_in[2];
    const float* eigval = (const float*)d_in[3];
    const float* Wq = (const float*)d_in[4];  const float* bq = (const float*)d_in[5];
    const float* Wk = (const float*)d_in[6];  const float* bk = (const float*)d_in[7];
    const float* Wv = (const float*)d_in[8];  const float* bv = (const float*)d_in[9];
    const float* Wo = (const float*)d_in[10]; const float* bo = (const float*)d_in[11];
    const float* Wp = (const float*)d_in[12]; const float* bp = (const float*)d_in[13];
    const float* W1 = (const float*)d_in[14]; const float* b1 = (const float*)d_in[15];
    const float* W2 = (const float*)d_in[16]; const float* b2 = (const float*)d_in[17];
    float* out = (float*)d_out;

    cudaFuncSetAttribute(k_attn, cudaFuncAttributeMaxDynamicSharedMemorySize, 120320);

    k_qkv  <<<BT*8,        256>>>(x, eigvec, eigval, Wq, bq, Wk, bk, Wv, bv);
    k_gat  <<<BT*Nn/8,     256>>>(adj, Wp, bp);
    k_topk <<<BT,          512>>>();
    k_attn <<<BT,          512, 120320>>>();
    k_value<<<BT*Nn/32,    256>>>(Wo, bo);
    k_ffn  <<<BT*Nn/32,    256>>>(W1, b1, W2, b2, out);
}

// round 2
// speedup vs baseline: 1.3917x; 1.3917x over previous
#include <cuda_runtime.h>

#define BT 96
#define Nn 512
#define Dd 64
#define NNb 16
#define MS 45

// ---------------- device scratch ----------------
__device__ float g_xq[BT*Nn*Dd];
__device__ float g_Q [BT*Nn*Dd];
__device__ float g_K [BT*Nn*Dd];
__device__ float g_V [BT*Nn*Dd];
__device__ float g_M [BT*Nn];
__device__ float g_av[BT*MS*Dd];
__device__ int   g_cp[BT*Nn];

// 64x64 GEMM tile core: 256 threads, thread (rg=tid>>4, j4=tid&15) computes
// rows rg*4..rg*4+3  x  cols j4*4..j4*4+3.  xsrc has row stride SF4 float4s.
template<int SF4>
__device__ __forceinline__ void gemm64(const float* __restrict__ xsrc,
                                       const float* __restrict__ w,
                                       const float* __restrict__ bias,
                                       float4 acc[4], int rg, int j4)
{
    float4 b4 = ((const float4*)bias)[j4];
    acc[0]=b4; acc[1]=b4; acc[2]=b4; acc[3]=b4;
    const float4* wp = (const float4*)w;
    const float4* xp = (const float4*)xsrc;
    #pragma unroll
    for (int d4 = 0; d4 < 16; d4++) {
        float4 w0 = wp[(d4*4+0)*16 + j4];
        float4 w1 = wp[(d4*4+1)*16 + j4];
        float4 w2 = wp[(d4*4+2)*16 + j4];
        float4 w3 = wp[(d4*4+3)*16 + j4];
        #pragma unroll
        for (int i = 0; i < 4; i++) {
            float4 xv = xp[(rg*4+i)*SF4 + d4];
            acc[i].x += xv.x*w0.x + xv.y*w1.x + xv.z*w2.x + xv.w*w3.x;
            acc[i].y += xv.x*w0.y + xv.y*w1.y + xv.z*w2.y + xv.w*w3.y;
            acc[i].z += xv.x*w0.z + xv.y*w1.z + xv.z*w2.z + xv.w*w3.z;
            acc[i].w += xv.x*w0.w + xv.y*w1.w + xv.z*w2.w + xv.w*w3.w;
        }
    }
}

// ---------------- K1: x_ = x + ev ; Q,K,V GEMMs ----------------
__global__ void k_qkv(const float* __restrict__ x, const float* __restrict__ eigvec,
                      const float* __restrict__ eigval,
                      const float* __restrict__ Wq, const float* __restrict__ bq,
                      const float* __restrict__ Wk, const float* __restrict__ bk,
                      const float* __restrict__ Wv, const float* __restrict__ bv)
{
    __shared__ __align__(16) float xs[4096];
    __shared__ __align__(16) float ws[4096];
    __shared__ __align__(16) float bs[64];
    int bt = blockIdx.x >> 3;
    int nb = (blockIdx.x & 7) * 64;
    int tid = threadIdx.x;

    for (int idx = tid; idx < 4096; idx += 256) {
        int r = idx >> 6, d = idx & 63;
        int n = nb + r;
        float v = x[(bt*Nn + n)*Dd + d] + eigvec[d*Nn + n] * eigval[d];
        xs[idx] = v;
        g_xq[(bt*Nn + n)*Dd + d] = v;
    }

    const float* Wm[3] = {Wq, Wk, Wv};
    const float* bm[3] = {bq, bk, bv};
    float* Om[3]; Om[0] = g_Q; Om[1] = g_K; Om[2] = g_V;

    int rg = tid >> 4, j4 = tid & 15;
    for (int m = 0; m < 3; m++) {
        __syncthreads();
        for (int idx = tid; idx < 4096; idx += 256) ws[idx] = Wm[m][idx];
        if (tid < 64) bs[tid] = bm[m][tid];
        __syncthreads();
        float4 acc[4];
        gemm64<16>(xs, ws, bs, acc, rg, j4);
        float* O = Om[m];
        int nbase = (bt*Nn + nb + rg*4)*Dd;
        #pragma unroll
        for (int i = 0; i < 4; i++)
            ((float4*)(O + nbase + i*Dd))[j4] = acc[i];
    }
}

// ---------------- K2: neighbor GAT -> M ----------------
__global__ void k_gat(const int* __restrict__ adj, const float* __restrict__ Wp,
                      const float* __restrict__ bp)
{
    int warp = threadIdx.x >> 5, lane = threadIdx.x & 31;
    int g = blockIdx.x * 8 + warp;
    int bt = g >> 9, n = g & 511;
    int base = bt*Nn*Dd;
    float2 q = ((const float2*)(g_Q + base + n*Dd))[lane];
    float ax = 0.f, ay = 0.f;
    #pragma unroll
    for (int k = 0; k < NNb; k++) {
        int j = adj[n*NNb + k];
        float2 kk = ((const float2*)(g_K + base + j*Dd))[lane];
        float p = q.x*kk.x + q.y*kk.y;
        #pragma unroll
        for (int o = 16; o; o >>= 1) p += __shfl_xor_sync(0xffffffffu, p, o);
        float2 vv = ((const float2*)(g_V + base + j*Dd))[lane];
        ax += p*vv.x; ay += p*vv.y;
    }
    float2 wp = ((const float2*)Wp)[lane];
    float mm = ax*wp.x + ay*wp.y;
    #pragma unroll
    for (int o = 16; o; o >>= 1) mm += __shfl_xor_sync(0xffffffffu, mm, o);
    if (lane == 0) g_M[g] = mm + bp[0];
}

// ---------------- K3: fused topk + scores + softmax + cp + AV ----------------
// dyn smem: sc[48*512] | qs[48*64] | ts[64*68] | ti[48]
__global__ void k_attn()
{
    extern __shared__ __align__(16) float sm[];
    float* sc = sm;                       // 24576 floats (attn matrix, padded 48 rows)
    float* qs = sm + 24576;               // 3072
    float* ts = qs + 3072;                // 4352  (tile, row stride 68)
    int*   ti = (int*)(ts + 4352);        // 48

    int bt = blockIdx.x, tid = threadIdx.x;   // 512 threads
    int base = bt*Nn*Dd;

    // ---- top-45 bitonic sort (reuse sc as u64 buffer) ----
    {
        unsigned long long* key = (unsigned long long*)sc;
        float f = g_M[bt*Nn + tid];
        unsigned int u = __float_as_uint(f);
        u = (u & 0x80000000u) ? ~u : (u | 0x80000000u);
        key[tid] = ((unsigned long long)u << 32) | (unsigned)tid;
        __syncthreads();
        for (int k = 2; k <= 512; k <<= 1)
            for (int j = k >> 1; j > 0; j >>= 1) {
                int ix = tid ^ j;
                if (ix > tid) {
                    bool up = ((tid & k) == 0);
                    unsigned long long a = key[tid], b = key[ix];
                    if ((a > b) == up) { key[tid] = b; key[ix] = a; }
                }
                __syncthreads();
            }
        if (tid < MS) ti[tid] = (int)(key[511 - tid] & 0xffffffffu);
        __syncthreads();
    }

    // ---- gather Q_red (48 rows, rows 45..47 zero) ----
    for (int idx = tid; idx < 48*64; idx += 512) {
        int m = idx >> 6, d = idx & 63;
        qs[idx] = (m < MS) ? g_Q[base + ti[m]*Dd + d] : 0.f;
    }

    // ---- scores: sc[m][n] = (qs[m]·K[n]) * 0.125 ----
    const float4* qs4 = (const float4*)qs;
    int mi = tid >> 5, ri = tid & 31;
    for (int t = 0; t < 8; t++) {
        __syncthreads();
        for (int idx = tid; idx < 1024; idx += 512) {
            int r = idx >> 4, d4 = idx & 15;
            ((float4*)ts)[r*17 + d4] = ((const float4*)(g_K + base))[(t*64 + r)*16 + d4];
        }
        __syncthreads();
        float s00=0,s01=0,s10=0,s11=0,s20=0,s21=0;
        const float4* tk = (const float4*)ts;
        #pragma unroll
        for (int d4 = 0; d4 < 16; d4++) {
            float4 q0 = qs4[(mi     )*16 + d4];
            float4 q1 = qs4[(mi + 16)*16 + d4];
            float4 q2 = qs4[(mi + 32)*16 + d4];
            float4 k0 = tk[ri*17 + d4];
            float4 k1 = tk[(ri+32)*17 + d4];
            s00 += q0.x*k0.x + q0.y*k0.y + q0.z*k0.z + q0.w*k0.w;
            s01 += q0.x*k1.x + q0.y*k1.y + q0.z*k1.z + q0.w*k1.w;
            s10 += q1.x*k0.x + q1.y*k0.y + q1.z*k0.z + q1.w*k0.w;
            s11 += q1.x*k1.x + q1.y*k1.y + q1.z*k1.z + q1.w*k1.w;
            s20 += q2.x*k0.x + q2.y*k0.y + q2.z*k0.z + q2.w*k0.w;
            s21 += q2.x*k1.x + q2.y*k1.y + q2.z*k1.z + q2.w*k1.w;
        }
        int nb = t*64;
        sc[(mi     )*512 + nb + ri     ] = s00*0.125f;
        sc[(mi     )*512 + nb + ri + 32] = s01*0.125f;
        sc[(mi + 16)*512 + nb + ri     ] = s10*0.125f;
        sc[(mi + 16)*512 + nb + ri + 32] = s11*0.125f;
        sc[(mi + 32)*512 + nb + ri     ] = s20*0.125f;
        sc[(mi + 32)*512 + nb + ri + 32] = s21*0.125f;
    }
    __syncthreads();

    // ---- softmax per m-row (warp per row, register-resident) ----
    {
        int warp = tid >> 5, lane = tid & 31;
        for (int m = warp; m < MS; m += 16) {
            float* row = sc + m*512;
            float rv[16];
            float mx = -1e30f;
            #pragma unroll
            for (int k = 0; k < 16; k++) { rv[k] = row[lane + 32*k]; mx = fmaxf(mx, rv[k]); }
            #pragma unroll
            for (int o = 16; o; o >>= 1) mx = fmaxf(mx, __shfl_xor_sync(0xffffffffu, mx, o));
            float s = 0.f;
            #pragma unroll
            for (int k = 0; k < 16; k++) { rv[k] = __expf(rv[k] - mx); s += rv[k]; }
            #pragma unroll
            for (int o = 16; o; o >>= 1) s += __shfl_xor_sync(0xffffffffu, s, o);
            float rinv = 1.f / s;
            #pragma unroll
            for (int k = 0; k < 16; k++) row[lane + 32*k] = rv[k]*rinv;
        }
        // zero padded rows 45..47
        for (int idx = tid; idx < 3*512; idx += 512)
            sc[(MS + (idx >> 9))*512 + (idx & 511)] = 0.f;
    }
    __syncthreads();

    // ---- cp = argmax_m attn[:,n]  (first-max ties, matching jnp.argmax) ----
    {
        int n = tid;
        float bv = sc[n]; int bi = 0;
        for (int m = 1; m < MS; m++) {
            float v = sc[m*512 + n];
            if (v > bv) { bv = v; bi = m; }
        }
        g_cp[bt*Nn + n] = bi;
    }

    // ---- av = attn @ V ----
    int di = tid & 31;   // mi reused from scores (tid>>5)
    float a00=0,a01=0,a10=0,a11=0,a20=0,a21=0;
    for (int t = 0; t < 8; t++) {
        __syncthreads();
        for (int idx = tid; idx < 1024; idx += 512) {
            int r = idx >> 4, d4 = idx & 15;
            ((float4*)ts)[r*17 + d4] = ((const float4*)(g_V + base))[(t*64 + r)*16 + d4];
        }
        __syncthreads();
        const float4* p0 = (const float4*)(sc + (mi     )*512 + t*64);
        const float4* p1 = (const float4*)(sc + (mi + 16)*512 + t*64);
        const float4* p2 = (const float4*)(sc + (mi + 32)*512 + t*64);
        #pragma unroll
        for (int r4 = 0; r4 < 16; r4++) {
            float4 w0 = p0[r4], w1 = p1[r4], w2 = p2[r4];
            float v0, v1;
            v0 = ts[(r4*4+0)*68 + di]; v1 = ts[(r4*4+0)*68 + di + 32];
            a00 += w0.x*v0; a01 += w0.x*v1; a10 += w1.x*v0; a11 += w1.x*v1; a20 += w2.x*v0; a21 += w2.x*v1;
            v0 = ts[(r4*4+1)*68 + di]; v1 = ts[(r4*4+1)*68 + di + 32];
            a00 += w0.y*v0; a01 += w0.y*v1; a10 += w1.y*v0; a11 += w1.y*v1; a20 += w2.y*v0; a21 += w2.y*v1;
            v0 = ts[(r4*4+2)*68 + di]; v1 = ts[(r4*4+2)*68 + di + 32];
            a00 += w0.z*v0; a01 += w0.z*v1; a10 += w1.z*v0; a11 += w1.z*v1; a20 += w2.z*v0; a21 += w2.z*v1;
            v0 = ts[(r4*4+3)*68 + di]; v1 = ts[(r4*4+3)*68 + di + 32];
            a00 += w0.w*v0; a01 += w0.w*v1; a10 += w1.w*v0; a11 += w1.w*v1; a20 += w2.w*v0; a21 += w2.w*v1;
        }
    }
    {
        float* av0 = g_av + (bt*MS + mi)*Dd;
        av0[di] = a00; av0[di + 32] = a01;
        float* av1 = g_av + (bt*MS + mi + 16)*Dd;
        av1[di] = a10; av1[di + 32] = a11;
        if (mi + 32 < MS) {
            float* av2 = g_av + (bt*MS + mi + 32)*Dd;
            av2[di] = a20; av2[di + 32] = a21;
        }
    }
}

// ---------------- K4: gather av[cp] -> Wo+res+LN -> FFN -> +res+LN -> out ----------------
// dyn smem: wo[4096] w1[4096] w2[4096] bs[192] xs[4352] vs[4352]
__global__ void k_out(const float* __restrict__ Wo, const float* __restrict__ bo,
                      const float* __restrict__ W1, const float* __restrict__ b1,
                      const float* __restrict__ W2, const float* __restrict__ b2,
                      float* __restrict__ out)
{
    extern __shared__ __align__(16) float sm[];
    float* wo = sm;
    float* w1 = sm + 4096;
    float* w2 = sm + 8192;
    float* bs = sm + 12288;   // 192
    float* xs = sm + 12480;   // 4352, row stride 68
    float* vs = xs + 4352;    // 4352

    int tid = threadIdx.x;    // 256
    int bt = blockIdx.x >> 3;
    int n0 = (blockIdx.x & 7) * 64;

    for (int idx = tid; idx < 4096; idx += 256) {
        wo[idx] = Wo[idx]; w1[idx] = W1[idx]; w2[idx] = W2[idx];
    }
    if (tid < 64) { bs[tid] = bo[tid]; bs[64+tid] = b1[tid]; bs[128+tid] = b2[tid]; }

    // gather xs[r] = g_av[cp(n0+r)]
    for (int idx = tid; idx < 1024; idx += 256) {
        int r = idx >> 4, d4 = idx & 15;
        int c = g_cp[bt*Nn + n0 + r];
        ((float4*)xs)[r*17 + d4] = ((const float4*)(g_av + (bt*MS + c)*Dd))[d4];
    }
    __syncthreads();

    int rg = tid >> 4, j4 = tid & 15;
    float4 acc[4];

    // GEMM1: value_pre = xs@Wo + bo + x_
    gemm64<17>(xs, wo, bs, acc, rg, j4);
    #pragma unroll
    for (int i = 0; i < 4; i++) {
        float4 xv = ((const float4*)(g_xq + (bt*Nn + n0 + rg*4 + i)*Dd))[j4];
        acc[i].x += xv.x; acc[i].y += xv.y; acc[i].z += xv.z; acc[i].w += xv.w;
        ((float4*)vs)[(rg*4+i)*17 + j4] = acc[i];
    }
    __syncthreads();

    // LN rows of vs
    {
        int warp = tid >> 5, lane = tid & 31;
        for (int r = warp; r < 64; r += 8) {
            float a = vs[r*68 + lane], b = vs[r*68 + lane + 32];
            float s = a + b;
            #pragma unroll
            for (int o = 16; o; o >>= 1) s += __shfl_xor_sync(0xffffffffu, s, o);
            float mu = s * (1.f/64.f);
            float da = a - mu, db = b - mu;
            float v2 = da*da + db*db;
            #pragma unroll
            for (int o = 16; o; o >>= 1) v2 += __shfl_xor_sync(0xffffffffu, v2, o);
            float rr = rsqrtf(v2*(1.f/64.f) + 1e-5f);
            vs[r*68 + lane] = da*rr; vs[r*68 + lane + 32] = db*rr;
        }
    }
    __syncthreads();

    // GEMM2: hs = relu(vs@W1 + b1) -> xs
    gemm64<17>(vs, w1, bs + 64, acc, rg, j4);
    #pragma unroll
    for (int i = 0; i < 4; i++) {
        acc[i].x = fmaxf(acc[i].x, 0.f); acc[i].y = fmaxf(acc[i].y, 0.f);
        acc[i].z = fmaxf(acc[i].z, 0.f); acc[i].w = fmaxf(acc[i].w, 0.f);
        ((float4*)xs)[(rg*4+i)*17 + j4] = acc[i];
    }
    __syncthreads();

    // GEMM3: h = xs@W2 + b2 + vs  -> vs
    gemm64<17>(xs, w2, bs + 128, acc, rg, j4);
    #pragma unroll
    for (int i = 0; i < 4; i++) {
        float4 vv = ((const float4*)vs)[(rg*4+i)*17 + j4];
        acc[i].x += vv.x; acc[i].y += vv.y; acc[i].z += vv.z; acc[i].w += vv.w;
    }
    __syncthreads();
    #pragma unroll
    for (int i = 0; i < 4; i++)
        ((float4*)vs)[(rg*4+i)*17 + j4] = acc[i];
    __syncthreads();

    // final LN -> out
    {
        int warp = tid >> 5, lane = tid & 31;
        for (int r = warp; r < 64; r += 8) {
            float a = vs[r*68 + lane], b = vs[r*68 + lane + 32];
            float s = a + b;
            #pragma unroll
            for (int o = 16; o; o >>= 1) s += __shfl_xor_sync(0xffffffffu, s, o);
            float mu = s * (1.f/64.f);
            float da = a - mu, db = b - mu;
            float v2 = da*da + db*db;
            #pragma unroll
            for (int o = 16; o; o >>= 1) v2 += __shfl_xor_sync(0xffffffffu, v2, o);
            float rr = rsqrtf(v2*(1.f/64.f) + 1e-5f);
            float* po = out + (bt*Nn + n0 + r)*Dd;
            po[lane] = da*rr; po[lane + 32] = db*rr;
        }
    }
}

// ---------------- launch ----------------
extern "C" void kernel_launch(void* const* d_in, const int* in_sizes, int n_in,
                              void* d_out, int out_size)
{
    const float* x      = (const float*)d_in[0];
    const int*   adj    = (const int*)  d_in[1];
    const float* eigvec = (const float*)d_in[2];
    const float* eigval = (const float*)d_in[3];
    const float* Wq = (const float*)d_in[4];  const float* bq = (const float*)d_in[5];
    const float* Wk = (const float*)d_in[6];  const float* bk = (const float*)d_in[7];
    const float* Wv = (const float*)d_in[8];  const float* bv = (const float*)d_in[9];
    const float* Wo = (const float*)d_in[10]; const float* bo = (const float*)d_in[11];
    const float* Wp = (const float*)d_in[12]; const float* bp = (const float*)d_in[13];
    const float* W1 = (const float*)d_in[14]; const float* b1 = (const float*)d_in[15];
    const float* W2 = (const float*)d_in[16]; const float* b2 = (const float*)d_in[17];
    float* out = (float*)d_out;

    cudaFuncSetAttribute(k_attn, cudaFuncAttributeMaxDynamicSharedMemorySize, 128192);
    cudaFuncSetAttribute(k_out,  cudaFuncAttributeMaxDynamicSharedMemorySize, 84736);

    k_qkv <<<BT*8,    256>>>(x, eigvec, eigval, Wq, bq, Wk, bk, Wv, bv);
    k_gat <<<BT*Nn/8, 256>>>(adj, Wp, bp);
    k_attn<<<BT,      512, 128192>>>();
    k_out <<<BT*8,    256, 84736>>>(Wo, bo, W1, b1, W2, b2, out);
}

// round 3
// speedup vs baseline: 1.5754x; 1.1320x over previous
#include <cuda_runtime.h>

#define BT 96
#define Nn 512
#define Dd 64
#define NNb 16
#define MS 45

// ---------------- device scratch ----------------
__device__ float g_xq[BT*Nn*Dd];
__device__ float g_Q [BT*Nn*Dd];
__device__ float g_K [BT*Nn*Dd];
__device__ float g_V [BT*Nn*Dd];
__device__ float g_M [BT*Nn];
__device__ float g_avo[BT*48*Dd];   // (av @ Wo + bo), 48 padded rows
__device__ int   g_cp[BT*Nn];

// ---------------- K1: x_ = x + ev ; Q,K,V GEMMs (interleaved, LDG weights) ----
__global__ void __launch_bounds__(256) k_qkv(
    const float* __restrict__ x, const float* __restrict__ eigvec,
    const float* __restrict__ eigval,
    const float* __restrict__ Wq, const float* __restrict__ bq,
    const float* __restrict__ Wk, const float* __restrict__ bk,
    const float* __restrict__ Wv, const float* __restrict__ bv)
{
    __shared__ __align__(16) float xs[4096];
    int bt = blockIdx.x >> 3;
    int nb = (blockIdx.x & 7) * 64;
    int tid = threadIdx.x;

    for (int idx = tid; idx < 4096; idx += 256) {
        int r = idx >> 6, d = idx & 63;
        int n = nb + r;
        float v = x[(bt*Nn + n)*Dd + d] + eigvec[d*Nn + n] * eigval[d];
        xs[idx] = v;
        g_xq[(bt*Nn + n)*Dd + d] = v;
    }
    __syncthreads();

    int rg = tid >> 4, j4 = tid & 15;
    const float4* wq4 = (const float4*)Wq;
    const float4* wk4 = (const float4*)Wk;
    const float4* wv4 = (const float4*)Wv;
    float4 aq[4], ak[4], av4[4];
    float4 bqv = __ldg((const float4*)bq + j4);
    float4 bkv = __ldg((const float4*)bk + j4);
    float4 bvv = __ldg((const float4*)bv + j4);
    #pragma unroll
    for (int i = 0; i < 4; i++) { aq[i] = bqv; ak[i] = bkv; av4[i] = bvv; }

    const float4* xp = (const float4*)xs;
    #pragma unroll
    for (int d4 = 0; d4 < 16; d4++) {
        float4 xr[4];
        #pragma unroll
        for (int i = 0; i < 4; i++) xr[i] = xp[(rg*4+i)*16 + d4];
        #pragma unroll
        for (int kk = 0; kk < 4; kk++) {
            float4 wq = __ldg(wq4 + (d4*4+kk)*16 + j4);
            float4 wk = __ldg(wk4 + (d4*4+kk)*16 + j4);
            float4 wv = __ldg(wv4 + (d4*4+kk)*16 + j4);
            #pragma unroll
            for (int i = 0; i < 4; i++) {
                float xv = ((const float*)&xr[i])[kk];
                aq[i].x += xv*wq.x; aq[i].y += xv*wq.y; aq[i].z += xv*wq.z; aq[i].w += xv*wq.w;
                ak[i].x += xv*wk.x; ak[i].y += xv*wk.y; ak[i].z += xv*wk.z; ak[i].w += xv*wk.w;
                av4[i].x += xv*wv.x; av4[i].y += xv*wv.y; av4[i].z += xv*wv.z; av4[i].w += xv*wv.w;
            }
        }
    }
    int nbase = (bt*Nn + nb + rg*4)*Dd;
    #pragma unroll
    for (int i = 0; i < 4; i++) {
        ((float4*)(g_Q + nbase + i*Dd))[j4] = aq[i];
        ((float4*)(g_K + nbase + i*Dd))[j4] = ak[i];
        ((float4*)(g_V + nbase + i*Dd))[j4] = av4[i];
    }
}

// ---------------- K2: neighbor GAT -> M ----------------
__global__ void k_gat(const int* __restrict__ adj, const float* __restrict__ Wp,
                      const float* __restrict__ bp)
{
    int warp = threadIdx.x >> 5, lane = threadIdx.x & 31;
    int g = blockIdx.x * 8 + warp;
    int bt = g >> 9, n = g & 511;
    int base = bt*Nn*Dd;
    float2 q = ((const float2*)(g_Q + base + n*Dd))[lane];
    float ax = 0.f, ay = 0.f;
    #pragma unroll
    for (int k = 0; k < NNb; k++) {
        int j = adj[n*NNb + k];
        float2 kk = ((const float2*)(g_K + base + j*Dd))[lane];
        float p = q.x*kk.x + q.y*kk.y;
        #pragma unroll
        for (int o = 16; o; o >>= 1) p += __shfl_xor_sync(0xffffffffu, p, o);
        float2 vv = ((const float2*)(g_V + base + j*Dd))[lane];
        ax += p*vv.x; ay += p*vv.y;
    }
    float2 wp = ((const float2*)Wp)[lane];
    float mm = ax*wp.x + ay*wp.y;
    #pragma unroll
    for (int o = 16; o; o >>= 1) mm += __shfl_xor_sync(0xffffffffu, mm, o);
    if (lane == 0) g_M[g] = mm + bp[0];
}

// ---------------- K3: topk + scores + softmax + cp + AV + avo GEMM ----------------
// dyn smem floats: sc[48*512] qs[48*64] ts[128*68] + ti[48] ints
__global__ void __launch_bounds__(1024) k_attn(const float* __restrict__ Wo,
                                               const float* __restrict__ bo)
{
    extern __shared__ __align__(16) float sm[];
    float* sc = sm;                       // 24576
    float* qs = sm + 24576;               // 3072
    float* ts = qs + 3072;                // 8704 (128 rows, stride 68)
    int*   ti = (int*)(ts + 8704);        // 48

    int bt = blockIdx.x, tid = threadIdx.x;   // 1024 threads
    int base = bt*Nn*Dd;

    // ---- top-45 bitonic (tid<512), sc reused as u64 buffer ----
    {
        unsigned long long* key = (unsigned long long*)sc;
        if (tid < 512) {
            float f = g_M[bt*Nn + tid];
            unsigned int u = __float_as_uint(f);
            u = (u & 0x80000000u) ? ~u : (u | 0x80000000u);
            key[tid] = ((unsigned long long)u << 32) | (unsigned)tid;
        }
        __syncthreads();
        for (int k = 2; k <= 512; k <<= 1)
            for (int j = k >> 1; j > 0; j >>= 1) {
                if (tid < 512) {
                    int ix = tid ^ j;
                    if (ix > tid) {
                        bool up = ((tid & k) == 0);
                        unsigned long long a = key[tid], b = key[ix];
                        if ((a > b) == up) { key[tid] = b; key[ix] = a; }
                    }
                }
                __syncthreads();
            }
        if (tid < MS) ti[tid] = (int)(key[511 - tid] & 0xffffffffu);
        __syncthreads();
    }

    // ---- gather Q_red (48 rows; 45..47 zero) ----
    for (int idx = tid; idx < 48*64; idx += 1024) {
        int m = idx >> 6, d = idx & 63;
        qs[idx] = (m < MS) ? g_Q[base + ti[m]*Dd + d] : 0.f;
    }

    const float4* qs4 = (const float4*)qs;
    int mi = tid >> 6, ri = tid & 63;

    // ---- scores: 4 tiles of 128 K-rows ----
    for (int t = 0; t < 4; t++) {
        __syncthreads();
        for (int idx = tid; idx < 2048; idx += 1024) {
            int r = idx >> 4, d4 = idx & 15;
            ((float4*)ts)[r*17 + d4] = ((const float4*)(g_K + base))[(t*128 + r)*16 + d4];
        }
        __syncthreads();
        float s00=0,s01=0,s10=0,s11=0,s20=0,s21=0;
        const float4* tk = (const float4*)ts;
        #pragma unroll
        for (int d4 = 0; d4 < 16; d4++) {
            float4 q0 = qs4[(mi     )*16 + d4];
            float4 q1 = qs4[(mi + 16)*16 + d4];
            float4 q2 = qs4[(mi + 32)*16 + d4];
            float4 k0 = tk[ri*17 + d4];
            float4 k1 = tk[(ri+64)*17 + d4];
            s00 += q0.x*k0.x + q0.y*k0.y + q0.z*k0.z + q0.w*k0.w;
            s01 += q0.x*k1.x + q0.y*k1.y + q0.z*k1.z + q0.w*k1.w;
            s10 += q1.x*k0.x + q1.y*k0.y + q1.z*k0.z + q1.w*k0.w;
            s11 += q1.x*k1.x + q1.y*k1.y + q1.z*k1.z + q1.w*k1.w;
            s20 += q2.x*k0.x + q2.y*k0.y + q2.z*k0.z + q2.w*k0.w;
            s21 += q2.x*k1.x + q2.y*k1.y + q2.z*k1.z + q2.w*k1.w;
        }
        int nb = t*128;
        sc[(mi     )*512 + nb + ri     ] = s00*0.125f;
        sc[(mi     )*512 + nb + ri + 64] = s01*0.125f;
        sc[(mi + 16)*512 + nb + ri     ] = s10*0.125f;
        sc[(mi + 16)*512 + nb + ri + 64] = s11*0.125f;
        sc[(mi + 32)*512 + nb + ri     ] = s20*0.125f;
        sc[(mi + 32)*512 + nb + ri + 64] = s21*0.125f;
    }
    __syncthreads();

    // ---- softmax (warp per row) ----
    {
        int warp = tid >> 5, lane = tid & 31;
        for (int m = warp; m < MS; m += 32) {
            float* row = sc + m*512;
            float rv[16];
            float mx = -1e30f;
            #pragma unroll
            for (int k = 0; k < 16; k++) { rv[k] = row[lane + 32*k]; mx = fmaxf(mx, rv[k]); }
            #pragma unroll
            for (int o = 16; o; o >>= 1) mx = fmaxf(mx, __shfl_xor_sync(0xffffffffu, mx, o));
            float s = 0.f;
            #pragma unroll
            for (int k = 0; k < 16; k++) { rv[k] = __expf(rv[k] - mx); s += rv[k]; }
            #pragma unroll
            for (int o = 16; o; o >>= 1) s += __shfl_xor_sync(0xffffffffu, s, o);
            float rinv = 1.f / s;
            #pragma unroll
            for (int k = 0; k < 16; k++) row[lane + 32*k] = rv[k]*rinv;
        }
        for (int idx = tid; idx < 3*512; idx += 1024) sc[MS*512 + idx] = 0.f;
    }
    __syncthreads();

    // ---- cp = argmax_m attn[:,n] (first-max ties) ----
    if (tid < 512) {
        int n = tid;
        float bv = sc[n]; int bi = 0;
        for (int m = 1; m < MS; m++) {
            float v = sc[m*512 + n];
            if (v > bv) { bv = v; bi = m; }
        }
        g_cp[bt*Nn + n] = bi;
    }

    // ---- av = attn @ V ----
    int di = ri;   // col
    float a0 = 0.f, a1 = 0.f, a2 = 0.f;
    for (int t = 0; t < 4; t++) {
        __syncthreads();
        for (int idx = tid; idx < 2048; idx += 1024) {
            int r = idx >> 4, d4 = idx & 15;
            ((float4*)ts)[r*17 + d4] = ((const float4*)(g_V + base))[(t*128 + r)*16 + d4];
        }
        __syncthreads();
        const float4* p0 = (const float4*)(sc + (mi     )*512 + t*128);
        const float4* p1 = (const float4*)(sc + (mi + 16)*512 + t*128);
        const float4* p2 = (const float4*)(sc + (mi + 32)*512 + t*128);
        #pragma unroll
        for (int r4 = 0; r4 < 32; r4++) {
            float4 w0 = p0[r4], w1 = p1[r4], w2 = p2[r4];
            float v;
            v = ts[(r4*4+0)*68 + di]; a0 += w0.x*v; a1 += w1.x*v; a2 += w2.x*v;
            v = ts[(r4*4+1)*68 + di]; a0 += w0.y*v; a1 += w1.y*v; a2 += w2.y*v;
            v = ts[(r4*4+2)*68 + di]; a0 += w0.z*v; a1 += w1.z*v; a2 += w2.z*v;
            v = ts[(r4*4+3)*68 + di]; a0 += w0.w*v; a1 += w1.w*v; a2 += w2.w*v;
        }
    }
    __syncthreads();
    qs[(mi     )*64 + di] = a0;
    qs[(mi + 16)*64 + di] = a1;
    qs[(mi + 32)*64 + di] = a2;
    __syncthreads();

    // ---- avo = av @ Wo + bo  (48x64 GEMM, LDG weights) ----
    {
        float b = __ldg(bo + di);
        float c0 = b, c1 = b, c2 = b;
        #pragma unroll
        for (int d4 = 0; d4 < 16; d4++) {
            float4 q0 = qs4[(mi     )*16 + d4];
            float4 q1 = qs4[(mi + 16)*16 + d4];
            float4 q2 = qs4[(mi + 32)*16 + d4];
            float w0 = __ldg(Wo + (d4*4+0)*64 + di);
            float w1 = __ldg(Wo + (d4*4+1)*64 + di);
            float w2 = __ldg(Wo + (d4*4+2)*64 + di);
            float w3 = __ldg(Wo + (d4*4+3)*64 + di);
            c0 += q0.x*w0 + q0.y*w1 + q0.z*w2 + q0.w*w3;
            c1 += q1.x*w0 + q1.y*w1 + q1.z*w2 + q1.w*w3;
            c2 += q2.x*w0 + q2.y*w1 + q2.z*w2 + q2.w*w3;
        }
        g_avo[(bt*48 + mi     )*64 + di] = c0;
        g_avo[(bt*48 + mi + 16)*64 + di] = c1;
        g_avo[(bt*48 + mi + 32)*64 + di] = c2;
    }
}

// ---------------- K4: gather avo[cp]+x_ -> LN -> FFN -> +res LN -> out ----------------
// dyn smem floats: vs[4352] hs[4352]
__global__ void __launch_bounds__(256) k_out(
    const float* __restrict__ W1, const float* __restrict__ b1,
    const float* __restrict__ W2, const float* __restrict__ b2,
    float* __restrict__ out)
{
    extern __shared__ __align__(16) float sm[];
    float* vs = sm;          // 64 rows, stride 68
    float* hs = sm + 4352;

    int tid = threadIdx.x;   // 256
    int bt = blockIdx.x >> 3;
    int n0 = (blockIdx.x & 7) * 64;

    // gather + residual
    for (int idx = tid; idx < 1024; idx += 256) {
        int r = idx >> 4, d4 = idx & 15;
        int c = g_cp[bt*Nn + n0 + r];
        float4 a = ((const float4*)(g_avo + (bt*48 + c)*Dd))[d4];
        float4 b = ((const float4*)(g_xq + (bt*Nn + n0 + r)*Dd))[d4];
        a.x += b.x; a.y += b.y; a.z += b.z; a.w += b.w;
        ((float4*)vs)[r*17 + d4] = a;
    }
    __syncthreads();

    // LN rows of vs
    {
        int warp = tid >> 5, lane = tid & 31;
        for (int r = warp; r < 64; r += 8) {
            float a = vs[r*68 + lane], b = vs[r*68 + lane + 32];
            float s = a + b;
            #pragma unroll
            for (int o = 16; o; o >>= 1) s += __shfl_xor_sync(0xffffffffu, s, o);
            float mu = s * (1.f/64.f);
            float da = a - mu, db = b - mu;
            float v2 = da*da + db*db;
            #pragma unroll
            for (int o = 16; o; o >>= 1) v2 += __shfl_xor_sync(0xffffffffu, v2, o);
            float rr = rsqrtf(v2*(1.f/64.f) + 1e-5f);
            vs[r*68 + lane] = da*rr; vs[r*68 + lane + 32] = db*rr;
        }
    }
    __syncthreads();

    int rg = tid >> 4, j4 = tid & 15;
    const float4* w14 = (const float4*)W1;
    const float4* w24 = (const float4*)W2;
    float4 acc[4];

    // GEMM: hs = relu(vs@W1 + b1)
    {
        float4 b4 = __ldg((const float4*)b1 + j4);
        #pragma unroll
        for (int i = 0; i < 4; i++) acc[i] = b4;
        const float4* xp = (const float4*)vs;
        #pragma unroll
        for (int d4 = 0; d4 < 16; d4++) {
            float4 xr[4];
            #pragma unroll
            for (int i = 0; i < 4; i++) xr[i] = xp[(rg*4+i)*17 + d4];
            #pragma unroll
            for (int kk = 0; kk < 4; kk++) {
                float4 w = __ldg(w14 + (d4*4+kk)*16 + j4);
                #pragma unroll
                for (int i = 0; i < 4; i++) {
                    float xv = ((const float*)&xr[i])[kk];
                    acc[i].x += xv*w.x; acc[i].y += xv*w.y; acc[i].z += xv*w.z; acc[i].w += xv*w.w;
                }
            }
        }
        #pragma unroll
        for (int i = 0; i < 4; i++) {
            acc[i].x = fmaxf(acc[i].x, 0.f); acc[i].y = fmaxf(acc[i].y, 0.f);
            acc[i].z = fmaxf(acc[i].z, 0.f); acc[i].w = fmaxf(acc[i].w, 0.f);
            ((float4*)hs)[(rg*4+i)*17 + j4] = acc[i];
        }
    }
    __syncthreads();

    // GEMM: o = hs@W2 + b2 + vs -> vs
    {
        float4 b4 = __ldg((const float4*)b2 + j4);
        #pragma unroll
        for (int i = 0; i < 4; i++) acc[i] = b4;
        const float4* xp = (const float4*)hs;
        #pragma unroll
        for (int d4 = 0; d4 < 16; d4++) {
            float4 xr[4];
            #pragma unroll
            for (int i = 0; i < 4; i++) xr[i] = xp[(rg*4+i)*17 + d4];
            #pragma unroll
            for (int kk = 0; kk < 4; kk++) {
                float4 w = __ldg(w24 + (d4*4+kk)*16 + j4);
                #pragma unroll
                for (int i = 0; i < 4; i++) {
                    float xv = ((const float*)&xr[i])[kk];
                    acc[i].x += xv*w.x; acc[i].y += xv*w.y; acc[i].z += xv*w.z; acc[i].w += xv*w.w;
                }
            }
        }
        #pragma unroll
        for (int i = 0; i < 4; i++) {
            float4 vv = ((const float4*)vs)[(rg*4+i)*17 + j4];
            acc[i].x += vv.x; acc[i].y += vv.y; acc[i].z += vv.z; acc[i].w += vv.w;
        }
        __syncthreads();
        #pragma unroll
        for (int i = 0; i < 4; i++)
            ((float4*)vs)[(rg*4+i)*17 + j4] = acc[i];
    }
    __syncthreads();

    // final LN -> out
    {
        int warp = tid >> 5, lane = tid & 31;
        for (int r = warp; r < 64; r += 8) {
            float a = vs[r*68 + lane], b = vs[r*68 + lane + 32];
            float s = a + b;
            #pragma unroll
            for (int o = 16; o; o >>= 1) s += __shfl_xor_sync(0xffffffffu, s, o);
            float mu = s * (1.f/64.f);
            float da = a - mu, db = b - mu;
            float v2 = da*da + db*db;
            #pragma unroll
            for (int o = 16; o; o >>= 1) v2 += __shfl_xor_sync(0xffffffffu, v2, o);
            float rr = rsqrtf(v2*(1.f/64.f) + 1e-5f);
            float* po = out + (bt*Nn + n0 + r)*Dd;
            po[lane] = da*rr; po[lane + 32] = db*rr;
        }
    }
}

// ---------------- launch ----------------
extern "C" void kernel_launch(void* const* d_in, const int* in_sizes, int n_in,
                              void* d_out, int out_size)
{
    const float* x      = (const float*)d_in[0];
    const int*   adj    = (const int*)  d_in[1];
    const float* eigvec = (const float*)d_in[2];
    const float* eigval = (const float*)d_in[3];
    const float* Wq = (const float*)d_in[4];  const float* bq = (const float*)d_in[5];
    const float* Wk = (const float*)d_in[6];  const float* bk = (const float*)d_in[7];
    const float* Wv = (const float*)d_in[8];  const float* bv = (const float*)d_in[9];
    const float* Wo = (const float*)d_in[10]; const float* bo = (const float*)d_in[11];
    const float* Wp = (const float*)d_in[12]; const float* bp = (const float*)d_in[13];
    const float* W1 = (const float*)d_in[14]; const float* b1 = (const float*)d_in[15];
    const float* W2 = (const float*)d_in[16]; const float* b2 = (const float*)d_in[17];
    float* out = (float*)d_out;

    cudaFuncSetAttribute(k_attn, cudaFuncAttributeMaxDynamicSharedMemorySize, 145600);
    cudaFuncSetAttribute(k_out,  cudaFuncAttributeMaxDynamicSharedMemorySize, 34816);

    k_qkv <<<BT*8,    256>>>(x, eigvec, eigval, Wq, bq, Wk, bk, Wv, bv);
    k_gat <<<BT*Nn/8, 256>>>(adj, Wp, bp);
    k_attn<<<BT,      1024, 145600>>>(Wo, bo);
    k_out <<<BT*8,    256, 34816>>>(W1, b1, W2, b2, out);
}